// round 7
// baseline (speedup 1.0000x reference)
#include <cuda_runtime.h>
#include <cstdint>
#include <math.h>

#define VSZ 128
#define HW  (VSZ*VSZ)          // 16384
#define NB  4
#define NP  32
#define PE  16
#define NE  (NP*PE)            // 512 edges per batch
#define EPSF  1e-8f
#define BIGF  3.4e38f

// ---------------- scratch (static device globals; no allocation) ------------
// per edge: A = {v0x, v0y, v1y, ex}; Bv = {ey, ex*inv, ey*inv, ex/(ey+eps)}
// polys compacted: active polys occupy slots [0,nact), sentinels after.
__device__ float4 g_edges[NB*NE*2];      // 64 KB
__device__ int    g_nact[NB];
__device__ int    g_hv[NB];

// ---------------- kernel A: setup + compaction (4 blocks x 256) -------------
__global__ __launch_bounds__(256) void setup_kernel(
    const float* __restrict__ polygons,
    const float* __restrict__ attributes,
    const float* __restrict__ validity)
{
    __shared__ float2 shv[NP][PE];
    __shared__ int    s_act[NP], s_K[NP], s_slot[NP];

    int w = threadIdx.x >> 5;     // warp 0..7, handles polys 4w..4w+3
    int l = threadIdx.x & 31;
    int b = blockIdx.x;

    #pragma unroll
    for (int i = 0; i < 4; i++) {
        int n = w*4 + i;
        int poly = b*NP + n;
        const float* pp = polygons + (size_t)poly * PE * 2;
        float x = 0.0f, y = 0.0f;
        bool valid = false;
        if (l < PE) {
            x = pp[2*l + 0];
            y = pp[2*l + 1];
            valid = (x + y) != 0.0f;
        }
        unsigned vm = __ballot_sync(0xffffffffu, valid);
        int K   = __popc(vm);
        int pos = __popc(vm & ((1u << l) - 1u));
        if (valid) shv[n][pos] = make_float2(x, y);
        if (l == 0) {
            s_K[n]   = K;
            s_act[n] = (K >= 3 && validity[poly] >= 0.5f) ? 1 : 0;
        }
    }
    __syncthreads();

    if (w == 0) {   // warp 0: compaction slots via ballot over 32 poly flags
        int flag = s_act[l];
        unsigned am = __ballot_sync(0xffffffffu, flag != 0);
        int nact  = __popc(am);
        int below = __popc(am & ((1u << l) - 1u));
        s_slot[l] = flag ? below : (nact + (l - below));
        if (l == 0) {
            g_nact[b] = nact;
            float av = attributes[b];                  // (B,1)
            av = fminf(fmaxf(av, 0.0f), 1.0f);
            int hv = (int)rintf(av * (float)VSZ);      // half-even, like jnp.rint
            g_hv[b] = min(max(hv, 1), VSZ);
        }
    }
    __syncthreads();

    #pragma unroll
    for (int i = 0; i < 4; i++) {
        int n = w*4 + i;
        int slot = s_slot[n];
        int K    = s_K[n];
        bool act = s_act[n] != 0;
        if (l < PE) {
            float4 A, Bv;
            if (act && l < K) {
                float2 v0 = shv[n][l];
                float2 v1 = shv[n][(l + 1 == K) ? 0 : l + 1];
                float ex = v1.x - v0.x;
                float ey = v1.y - v0.y;
                float inv = 1.0f / (ex*ex + ey*ey + EPSF);
                A  = make_float4(v0.x, v0.y, v1.y, ex);
                Bv = make_float4(ey, ex*inv, ey*inv, ex / (ey + EPSF));
            } else {
                A  = make_float4(0.0f, 1e30f, 1e30f, 0.0f);   // sentinel
                Bv = make_float4(0.0f, 0.0f, 0.0f, 0.0f);
            }
            size_t eidx = ((size_t)(b*NP + slot) * PE + l) * 2;
            g_edges[eidx + 0] = A;
            g_edges[eidx + 1] = Bv;
        }
    }
}

// one edge distance step; R={c1, vy, v0x, ix_enc}  E={ex, ey, ex*inv, 0}
#define EDGE1(Rp, Ep, e, m2)                                    \
    {                                                           \
        float4 R = (Rp)[e];                                     \
        float4 E = (Ep)[e];                                     \
        float tt = __saturatef(fmaf(px, E.z, R.x));             \
        float u  = px - R.z;                                    \
        float dx = fmaf(-E.x, tt, u);                           \
        float dy = fmaf(-E.y, tt, R.y);                         \
        float d2 = fmaf(dy, dy, dx*dx);                         \
        m2 = fminf(m2, d2);                                     \
    }

// ------- kernel B: fused SDF + mask + depth broadcast (128 x 512) -----------
__global__ __launch_bounds__(512) void fused_kernel(float* __restrict__ out)
{
    __shared__ float4   sRE[4*NE];                 // {c1, vy, v0x, ix_enc}  32KB
    __shared__ float4   sEC[NE];                   // {ex, ey, ex*inv, 0}     8KB
    __shared__ unsigned s_par[512];                // parity bitmaps          2KB
    __shared__ __align__(16) float s_cmb[512];     // combined tile           2KB
    __shared__ __align__(16) float s_zero[512];    // zero tile               2KB
    __shared__ int    s_nact, s_hv;

    int b    = blockIdx.x >> 5;       // 32 tiles per batch
    int tile = blockIdx.x & 31;
    int t    = threadIdx.x;

    const float hstep = 1.0f / (float)(VSZ - 1);
    const float4* ge = g_edges + (size_t)b * NE * 2;

    // ---- phase 1: row-edge table (2048 entries, 4 per thread) ----
    #pragma unroll
    for (int k = 0; k < 4; k++) {
        int i    = t + 512*k;
        int rr   = i >> 9;            // row within block
        int eidx = i & (NE - 1);
        float4 A  = ge[eidx*2 + 0];   // v0x, v0y, v1y, ex
        float4 Bv = ge[eidx*2 + 1];   // ey, ex*inv, ey*inv, ex/(ey+eps)
        float py  = (float)(tile*4 + rr) * hstep;
        float vy  = py - A.y;
        bool  yc  = (A.y <= py) != (A.z <= py);
        float ix  = fmaf(Bv.w, vy, A.x);
        float c1  = fmaf(-A.x, Bv.y, vy * Bv.z);   // t = px*(ex*inv) + c1
        sRE[i] = make_float4(c1, vy, A.x, yc ? ix : -BIGF);
        if (k == 0)                    // rr==0 here; also fill edge constants
            sEC[eidx] = make_float4(A.w, Bv.x, Bv.y, 0.0f);
    }
    s_zero[t] = 0.0f;
    if (t == 0) { s_nact = g_nact[b]; s_hv = g_hv[b]; }
    __syncthreads();

    // ---- phase 2: crossing-parity bitmaps ----
    // thread t = row*128 + poly*4 + word builds bits for px in [32w,32w+32):
    // bit j set iff (float)j*hstep < ix  (exact wrt the float compare).
    {
        int rowp = t >> 7;
        int poly = (t >> 2) & 31;
        int wsel = t & 3;
        int lo   = wsel * 32;
        unsigned acc = 0u;
        const float4* Rp = sRE + rowp*NE + poly*PE;
        #pragma unroll
        for (int e = 0; e < PE; e++) {
            float ix = Rp[e].w;
            float jf = ix * 127.0f;
            int c = (int)fminf(fmaxf(ceilf(jf), 0.0f), 128.0f);
            while (c < 128 && (float)c * hstep < ix) c++;
            while (c > 0 && (float)(c-1) * hstep >= ix) c--;
            unsigned wm;
            int rel = c - lo;
            if (rel <= 0)       wm = 0u;
            else if (rel >= 32) wm = 0xffffffffu;
            else                wm = (1u << rel) - 1u;
            acc ^= wm;
        }
        s_par[t] = acc;
    }
    __syncthreads();

    int   rr   = t >> 7;
    int   lane = t & 31;
    int   wsel = (t >> 5) & 3;
    float px   = (float)(t & (VSZ-1)) * hstep;
    const float4* REr = sRE + rr * NE;
    const unsigned* PAR = s_par + rr * (NP*4) + wsel;

    // min over polys of signed d^2 (sign injected from parity bitmap)
    float S = BIGF;
    int np2 = (s_nact + 1) >> 1;      // slots [nact,32) are sentinels -> +inf
    for (int i = 0; i < np2; i++) {
        int p0 = i, p1 = i + np2;
        const float4* Rp0 = REr + p0*PE;
        const float4* Rp1 = REr + p1*PE;
        const float4* Ep0 = sEC + p0*PE;
        const float4* Ep1 = sEC + p1*PE;
        float m20 = BIGF, m21 = BIGF;
        #pragma unroll
        for (int e = 0; e < PE; e++) {
            EDGE1(Rp0, Ep0, e, m20);
            EDGE1(Rp1, Ep1, e, m21);
        }
        unsigned sg0 = (PAR[p0*4] << (31 - lane)) & 0x80000000u;
        unsigned sg1 = (PAR[p1*4] << (31 - lane)) & 0x80000000u;
        float s0 = __uint_as_float(__float_as_uint(m20) ^ sg0);
        float s1 = __uint_as_float(__float_as_uint(m21) ^ sg1);
        S = fminf(S, fminf(s0, s1));
        // saturation exit: sdf < -0.1 for all lanes -> mask within 4.5e-5 of 1
        if (__all_sync(0xffffffffu, S < -0.01f)) break;
    }

    float d   = sqrtf(fabsf(S));
    float sdf = (S < 0.0f) ? -d : d;
    float v   = __fdividef(1.0f, 1.0f + __expf(100.0f * sdf));

    // ---- stage tile, then depth-broadcast with async bulk copies ----
    s_cmb[t] = v;
    __syncthreads();

    if (t < VSZ) {
        asm volatile("fence.proxy.async.shared::cta;" ::: "memory");
        int dz = t;                                  // depth slice
        const float* srcp = (dz < s_hv) ? s_cmb : s_zero;
        unsigned int saddr;
        asm("{ .reg .u64 a; cvta.to.shared.u64 a, %1; cvt.u32.u64 %0, a; }"
            : "=r"(saddr) : "l"(srcp));
        float* gdst = out + ((size_t)b * VSZ + dz) * HW + tile * 512;
        asm volatile("cp.async.bulk.global.shared::cta.bulk_group [%0], [%1], %2;"
                     :: "l"(gdst), "r"(saddr), "r"(512u * 4u) : "memory");
        asm volatile("cp.async.bulk.commit_group;" ::: "memory");
        asm volatile("cp.async.bulk.wait_group 0;" ::: "memory");
    }
}

// ---------------- launch ----------------------------------------------------
extern "C" void kernel_launch(void* const* d_in, const int* in_sizes, int n_in,
                              void* d_out, int out_size)
{
    const float* polygons   = (const float*)d_in[0];   // (4,32,16,2)
    const float* attributes = (const float*)d_in[1];   // (4,1)
    const float* validity   = (const float*)d_in[2];   // (4,32)
    float* out = (float*)d_out;                        // (4,128,128,128)

    setup_kernel<<<NB, 256>>>(polygons, attributes, validity);
    fused_kernel<<<NB*32, 512>>>(out);
}

// round 8
// speedup vs baseline: 1.1015x; 1.1015x over previous
#include <cuda_runtime.h>
#include <cstdint>
#include <math.h>

#define VSZ 128
#define HW  (VSZ*VSZ)          // 16384
#define NB  4
#define NP  32
#define PE  16
#define NE  (NP*PE)            // 512 edges per batch
#define EPSF  1e-8f
#define BIGF  3.4e38f

// ---------------- scratch (static device globals; no allocation) ------------
// per edge: A = {v0x, v0y, v1y, ex}; Bv = {ey, ex*inv, ey*inv, ex/(ey+eps)}
// polys compacted: active polys occupy slots [0,nact), sentinels after.
__device__ float4 g_edges[NB*NE*2];      // 64 KB
__device__ int    g_nact[NB];
__device__ int    g_hv[NB];

// ---------------- kernel A: setup + compaction (4 blocks x 256) -------------
__global__ __launch_bounds__(256) void setup_kernel(
    const float* __restrict__ polygons,
    const float* __restrict__ attributes,
    const float* __restrict__ validity)
{
    __shared__ float2 shv[NP][PE];
    __shared__ int    s_act[NP], s_K[NP], s_slot[NP];

    int w = threadIdx.x >> 5;     // warp 0..7, handles polys 4w..4w+3
    int l = threadIdx.x & 31;
    int b = blockIdx.x;

    #pragma unroll
    for (int i = 0; i < 4; i++) {
        int n = w*4 + i;
        int poly = b*NP + n;
        const float* pp = polygons + (size_t)poly * PE * 2;
        float x = 0.0f, y = 0.0f;
        bool valid = false;
        if (l < PE) {
            x = pp[2*l + 0];
            y = pp[2*l + 1];
            valid = (x + y) != 0.0f;
        }
        unsigned vm = __ballot_sync(0xffffffffu, valid);
        int K   = __popc(vm);
        int pos = __popc(vm & ((1u << l) - 1u));
        if (valid) shv[n][pos] = make_float2(x, y);
        if (l == 0) {
            s_K[n]   = K;
            s_act[n] = (K >= 3 && validity[poly] >= 0.5f) ? 1 : 0;
        }
    }
    __syncthreads();

    if (w == 0) {   // warp 0: compaction slots via ballot over 32 poly flags
        int flag = s_act[l];
        unsigned am = __ballot_sync(0xffffffffu, flag != 0);
        int nact  = __popc(am);
        int below = __popc(am & ((1u << l) - 1u));
        s_slot[l] = flag ? below : (nact + (l - below));
        if (l == 0) {
            g_nact[b] = nact;
            float av = attributes[b];                  // (B,1)
            av = fminf(fmaxf(av, 0.0f), 1.0f);
            int hv = (int)rintf(av * (float)VSZ);      // half-even, like jnp.rint
            g_hv[b] = min(max(hv, 1), VSZ);
        }
    }
    __syncthreads();

    #pragma unroll
    for (int i = 0; i < 4; i++) {
        int n = w*4 + i;
        int slot = s_slot[n];
        int K    = s_K[n];
        bool act = s_act[n] != 0;
        if (l < PE) {
            float4 A, Bv;
            if (act && l < K) {
                float2 v0 = shv[n][l];
                float2 v1 = shv[n][(l + 1 == K) ? 0 : l + 1];
                float ex = v1.x - v0.x;
                float ey = v1.y - v0.y;
                float inv = 1.0f / (ex*ex + ey*ey + EPSF);
                A  = make_float4(v0.x, v0.y, v1.y, ex);
                Bv = make_float4(ey, ex*inv, ey*inv, ex / (ey + EPSF));
            } else {
                A  = make_float4(0.0f, 1e30f, 1e30f, 0.0f);   // sentinel
                Bv = make_float4(0.0f, 0.0f, 0.0f, 0.0f);
            }
            size_t eidx = ((size_t)(b*NP + slot) * PE + l) * 2;
            g_edges[eidx + 0] = A;
            g_edges[eidx + 1] = Bv;
        }
    }
}

// one edge step: distance + crossing. R={c1, ix_enc, vy, v0x}  E={ex,ey,exinv}
#define EDGE1(Rp, Ep, e, m2, cnt)                               \
    {                                                           \
        float4 R = (Rp)[e];                                     \
        float4 E = (Ep)[e];                                     \
        float tt = __saturatef(fmaf(px, E.z, R.x));             \
        float u  = px - R.w;                                    \
        float dx = fmaf(-E.x, tt, u);                           \
        float dy = fmaf(-E.y, tt, R.z);                         \
        float d2 = fmaf(dy, dy, dx*dx);                         \
        m2 = fminf(m2, d2);                                     \
        cnt ^= (R.y > px) ? 1u : 0u;                            \
    }

// ------- kernel B: fused SDF + mask + depth broadcast (128 x 512) -----------
// Block covers 4 rows (512 px) of one batch; row-dependent edge terms hoisted
// per (row, edge); 2 polygons processed in interleaved independent streams;
// depth broadcast via cp.async.bulk (2KB per depth slice).
__global__ __launch_bounds__(512) void fused_kernel(float* __restrict__ out)
{
    __shared__ float4 sRE[4*NE];                   // {c1, ix_enc, vy, v0x}  32KB
    __shared__ float4 sEC[NE];                     // {ex, ey, ex*inv, 0}     8KB
    __shared__ __align__(16) float s_cmb[512];     // combined tile           2KB
    __shared__ __align__(16) float s_zero[512];    // zero tile               2KB
    __shared__ int    s_nact, s_hv;

    int b    = blockIdx.x >> 5;       // 32 tiles per batch
    int tile = blockIdx.x & 31;
    int t    = threadIdx.x;

    const float hstep = 1.0f / (float)(VSZ - 1);
    const float4* ge = g_edges + (size_t)b * NE * 2;

    // ---- phase 1: row-edge table (2048 entries, 4 per thread) ----
    #pragma unroll
    for (int k = 0; k < 4; k++) {
        int i    = t + 512*k;
        int rr   = i >> 9;            // row within block
        int eidx = i & (NE - 1);
        float4 A  = ge[eidx*2 + 0];   // v0x, v0y, v1y, ex
        float4 Bv = ge[eidx*2 + 1];   // ey, ex*inv, ey*inv, ex/(ey+eps)
        float py  = (float)(tile*4 + rr) * hstep;
        float vy  = py - A.y;
        bool  yc  = (A.y <= py) != (A.z <= py);
        float ix  = fmaf(Bv.w, vy, A.x);
        float c1  = fmaf(-A.x, Bv.y, vy * Bv.z);   // t = px*(ex*inv) + c1
        sRE[i] = make_float4(c1, yc ? ix : -BIGF, vy, A.x);
        if (k == 0)                    // rr==0 here; also fill edge constants
            sEC[eidx] = make_float4(A.w, Bv.x, Bv.y, 0.0f);
    }
    s_zero[t] = 0.0f;
    if (t == 0) { s_nact = g_nact[b]; s_hv = g_hv[b]; }
    __syncthreads();

    int   rr = t >> 7;
    float px = (float)(t & (VSZ-1)) * hstep;
    const float4* REr = sRE + rr * NE;

    // min over polys of signed d^2 (monotone map of signed distance);
    // two interleaved independent polygon streams for ILP, no early exit.
    float S0 = BIGF, S1 = BIGF;
    int np2 = (s_nact + 1) >> 1;      // sentinel slots give +inf, no crossings
    for (int i = 0; i < np2; i++) {
        int p0 = i, p1 = i + np2;
        const float4* Rp0 = REr + p0*PE;
        const float4* Rp1 = REr + p1*PE;
        const float4* Ep0 = sEC + p0*PE;
        const float4* Ep1 = sEC + p1*PE;
        float m20 = BIGF, m21 = BIGF;
        unsigned c0 = 0u, c1c = 0u;
        #pragma unroll
        for (int e = 0; e < PE; e++) {
            EDGE1(Rp0, Ep0, e, m20, c0);
            EDGE1(Rp1, Ep1, e, m21, c1c);
        }
        float s0 = __uint_as_float(__float_as_uint(m20) ^ (c0  << 31));
        float s1 = __uint_as_float(__float_as_uint(m21) ^ (c1c << 31));
        S0 = fminf(S0, s0);
        S1 = fminf(S1, s1);
    }
    float S = fminf(S0, S1);

    float d   = sqrtf(fabsf(S));
    float sdf = (S < 0.0f) ? -d : d;
    float v   = __fdividef(1.0f, 1.0f + __expf(100.0f * sdf));

    // ---- stage tile, then depth-broadcast with async bulk copies ----
    s_cmb[t] = v;
    __syncthreads();

    if (t < VSZ) {
        asm volatile("fence.proxy.async.shared::cta;" ::: "memory");
        int dz = t;                                  // depth slice
        const float* srcp = (dz < s_hv) ? s_cmb : s_zero;
        unsigned int saddr;
        asm("{ .reg .u64 a; cvta.to.shared.u64 a, %1; cvt.u32.u64 %0, a; }"
            : "=r"(saddr) : "l"(srcp));
        float* gdst = out + ((size_t)b * VSZ + dz) * HW + tile * 512;
        asm volatile("cp.async.bulk.global.shared::cta.bulk_group [%0], [%1], %2;"
                     :: "l"(gdst), "r"(saddr), "r"(512u * 4u) : "memory");
        asm volatile("cp.async.bulk.commit_group;" ::: "memory");
        asm volatile("cp.async.bulk.wait_group 0;" ::: "memory");
    }
}

// ---------------- launch ----------------------------------------------------
extern "C" void kernel_launch(void* const* d_in, const int* in_sizes, int n_in,
                              void* d_out, int out_size)
{
    const float* polygons   = (const float*)d_in[0];   // (4,32,16,2)
    const float* attributes = (const float*)d_in[1];   // (4,1)
    const float* validity   = (const float*)d_in[2];   // (4,32)
    float* out = (float*)d_out;                        // (4,128,128,128)

    setup_kernel<<<NB, 256>>>(polygons, attributes, validity);
    fused_kernel<<<NB*32, 512>>>(out);
}